// round 10
// baseline (speedup 1.0000x reference)
#include <cuda_runtime.h>
#include <cstdint>

#define BB    64
#define SS    1024
#define HH    1000
#define SPLIT 16
#define CHUNK (SS / SPLIT)    /* 64 rows per CTA */
#define WPB   4               /* warps per block */
#define RPW   (CHUNK / WPB)   /* 16 rows per warp */
#define H4    250             /* float4 per row */

#define VKS   8               /* K-splits for v kernel */
#define VGP   125             /* g per K-split */

// Scratch (static device arrays: allocation-free per harness rules)
__device__ __align__(16) float g_vp[VKS * BB * HH];     // 2 MB   v K-partials
__device__ __align__(16) float g_v[BB * HH];            // 256 KB v = h_tgt @ W
__device__ __align__(16) float g_part[SPLIT * BB * HH]; // 4 MB   acc per split
__device__ float g_ml[SPLIT * BB * 2];                  // (m, l) per split
__device__ int   g_cnt_v[16];                           // arrival ctr per h-chunk
__device__ int   g_cnt_a[BB];                           // arrival ctr per batch

// ---------------------------------------------------------------------------
// Kernel 1: v = h_tgt @ W. grid (16 h-chunks x 8 K-splits) = 128 CTAs.
// Each CTA handles ALL 64 batches for its (64-col h-chunk, 125-row K-chunk):
// W is read EXACTLY ONCE across the grid (4 MB, was 64 MB).
// Last CTA per h-chunk reduces the 8 K-partials in fixed order (deterministic).
// ---------------------------------------------------------------------------
__global__ __launch_bounds__(256) void v_kernel(
    const float* __restrict__ h_tgt, const float* __restrict__ Wm)
{
    __shared__ float stg[64 * VGP];      // h_tgt slice [b][gi], 32 KB
    __shared__ int isLast;
    const int hb = blockIdx.x;           // 0..15
    const int ks = blockIdx.y;           // 0..7
    const int h0 = hb * 64, g0 = ks * VGP;
    const int t = threadIdx.x;

    for (int i = t; i < 64 * VGP; i += 256) {
        int b = i / VGP, gi = i - b * VGP;
        stg[i] = h_tgt[b * HH + g0 + gi];
    }
    __syncthreads();

    const int q = t & 15, bg = t >> 4;   // h-quad, batch-group(4)
    const int h = h0 + q * 4;
    const bool hok = (h + 3) < HH;

    if (hok) {
        float4 acc[4];
        #pragma unroll
        for (int i = 0; i < 4; i++) acc[i] = make_float4(0.f, 0.f, 0.f, 0.f);

        #pragma unroll 5
        for (int gi = 0; gi < VGP; gi++) {
            float4 w4 = __ldg((const float4*)(Wm + (size_t)(g0 + gi) * HH + h));
            #pragma unroll
            for (int bb = 0; bb < 4; bb++) {
                float tb = stg[(bg * 4 + bb) * VGP + gi];
                acc[bb].x += tb * w4.x;
                acc[bb].y += tb * w4.y;
                acc[bb].z += tb * w4.z;
                acc[bb].w += tb * w4.w;
            }
        }
        #pragma unroll
        for (int bb = 0; bb < 4; bb++)
            *((float4*)(g_vp + ((size_t)ks * BB + bg * 4 + bb) * HH + h)) = acc[bb];
    }

    __threadfence();
    if (t == 0) isLast = (atomicAdd(&g_cnt_v[hb], 1) == VKS - 1);
    __syncthreads();
    if (!isLast) return;
    __threadfence();   // acquire: see all K-partials

    for (int slot = t; slot < 64 * 16; slot += 256) {
        int b = slot >> 4, qq = slot & 15;
        int h2 = h0 + qq * 4;
        if (h2 + 3 < HH) {
            float4 s = make_float4(0.f, 0.f, 0.f, 0.f);
            #pragma unroll
            for (int k = 0; k < VKS; k++) {
                float4 x = *((const float4*)(g_vp + ((size_t)k * BB + b) * HH + h2));
                s.x += x.x; s.y += x.y; s.z += x.z; s.w += x.w;
            }
            *((float4*)(g_v + (size_t)b * HH + h2)) = s;
        }
    }
    __syncthreads();
    if (t == 0) atomicExch(&g_cnt_v[hb], 0);   // reset for graph replay
}

// ---------------------------------------------------------------------------
// Kernel 2: warp-autonomous streaming attention + fused combine.
// PAIR processing: score 2 rows, interleaved shfl reductions (one latency),
// one softmax update per pair, and next-pair LDGs issued INSIDE the acc pass
// right after each A[j]/B[j]'s last use -> 8KB in flight per warp with zero
// extra registers. __ldcg streaming loads (skip L1).
// ---------------------------------------------------------------------------
__device__ __forceinline__ void load_row(float4 (&buf)[8],
                                         const float4* __restrict__ p, int lane)
{
    #pragma unroll
    for (int j = 0; j < 7; j++) buf[j] = __ldcg(p + lane + 32 * j);
    buf[7] = make_float4(0.f, 0.f, 0.f, 0.f);
    if (lane < 26) buf[7] = __ldcg(p + 224 + lane);
}

__global__ __launch_bounds__(128) void attn_fused_kernel(
    const float* __restrict__ h_src, float* __restrict__ out)
{
    __shared__ __align__(16) float sv[1024];   // 4 KB v
    __shared__ float4 sacc[WPB][256];          // 16 KB warp partials
    __shared__ float  sml[WPB][2];
    __shared__ float  sgw[SPLIT];
    __shared__ float  sInv;
    __shared__ int    isLast;

    const int sp = blockIdx.x, b = blockIdx.y;
    const int t = threadIdx.x, lane = t & 31, w = t >> 5;

    const float4* rp = (const float4*)(h_src +
        ((size_t)b * SS + (size_t)sp * CHUNK + (size_t)w * RPW) * HH);

    float4 A[8], B[8];
    load_row(A, rp, lane);               // pair 0 in flight before sv barrier
    load_row(B, rp + H4, lane);

    for (int i = t; i < HH; i += 128) sv[i] = g_v[b * HH + i];
    __syncthreads();
    const float4* v4 = (const float4*)sv;

    float m = -1e30f, l = 0.f;
    float4 acc[8];
    #pragma unroll
    for (int j = 0; j < 8; j++) acc[j] = make_float4(0.f, 0.f, 0.f, 0.f);

    #pragma unroll 1
    for (int i = 0; i < RPW; i += 2) {
        // Scores for both rows (independent partials)
        float sa0 = 0.f, sa1 = 0.f, sb0 = 0.f, sb1 = 0.f;
        #pragma unroll
        for (int j = 0; j < 7; j++) {
            float4 v = v4[lane + 32 * j];
            sa0 += A[j].x * v.x + A[j].z * v.z;
            sa1 += A[j].y * v.y + A[j].w * v.w;
            sb0 += B[j].x * v.x + B[j].z * v.z;
            sb1 += B[j].y * v.y + B[j].w * v.w;
        }
        if (lane < 26) {
            float4 v = v4[224 + lane];
            sa0 += A[7].x * v.x + A[7].z * v.z;
            sa1 += A[7].y * v.y + A[7].w * v.w;
            sb0 += B[7].x * v.x + B[7].z * v.z;
            sb1 += B[7].y * v.y + B[7].w * v.w;
        }
        float sA = sa0 + sa1, sB = sb0 + sb1;
        // Interleaved reductions: two independent chains overlap in latency
        #pragma unroll
        for (int o = 16; o; o >>= 1) {
            sA += __shfl_xor_sync(0xffffffffu, sA, o);
            sB += __shfl_xor_sync(0xffffffffu, sB, o);
        }

        // One softmax update for the pair
        float nm   = fmaxf(m, fmaxf(sA, sB));
        float corr = __expf(m - nm);
        float pA   = __expf(sA - nm);
        float pB   = __expf(sB - nm);
        m = nm;
        l = l * corr + pA + pB;

        // Next-pair pointers (clamped on last iter; values then unused)
        const bool more = (i + 2) < RPW;
        const float4* nA = more ? rp + 2 * H4 : rp;
        const float4* nB = more ? rp + 3 * H4 : rp;

        // Fused accumulate + prefetch: overwrite A[j]/B[j] right after last use
        #pragma unroll
        for (int j = 0; j < 7; j++) {
            float4 a = A[j], bb = B[j];
            A[j] = __ldcg(nA + lane + 32 * j);
            B[j] = __ldcg(nB + lane + 32 * j);
            acc[j].x = acc[j].x * corr + pA * a.x + pB * bb.x;
            acc[j].y = acc[j].y * corr + pA * a.y + pB * bb.y;
            acc[j].z = acc[j].z * corr + pA * a.z + pB * bb.z;
            acc[j].w = acc[j].w * corr + pA * a.w + pB * bb.w;
        }
        {
            float4 a = A[7], bb = B[7];
            if (lane < 26) {
                A[7] = __ldcg(nA + 224 + lane);
                B[7] = __ldcg(nB + 224 + lane);
            }
            acc[7].x = acc[7].x * corr + pA * a.x + pB * bb.x;
            acc[7].y = acc[7].y * corr + pA * a.y + pB * bb.y;
            acc[7].z = acc[7].z * corr + pA * a.z + pB * bb.z;
            acc[7].w = acc[7].w * corr + pA * a.w + pB * bb.w;
        }
        rp += 2 * H4;
    }

    // Merge 4 warp partials within CTA
    #pragma unroll
    for (int j = 0; j < 7; j++) sacc[w][lane + 32 * j] = acc[j];
    if (lane < 26) sacc[w][224 + lane] = acc[7];
    if (lane == 0) { sml[w][0] = m; sml[w][1] = l; }
    __syncthreads();

    float M = fmaxf(fmaxf(sml[0][0], sml[1][0]), fmaxf(sml[2][0], sml[3][0]));
    float L = 0.f;
    float wgt[WPB];
    #pragma unroll
    for (int i = 0; i < WPB; i++) {
        wgt[i] = __expf(sml[i][0] - M);
        L += sml[i][1] * wgt[i];
    }

    float4* dst = (float4*)(g_part + (size_t)(sp * BB + b) * HH);
    #pragma unroll
    for (int rep = 0; rep < 2; rep++) {
        int slot = t + rep * 128;
        if (slot < H4) {
            float4 o = make_float4(0.f, 0.f, 0.f, 0.f);
            #pragma unroll
            for (int i = 0; i < WPB; i++) {
                float4 x = sacc[i][slot];
                o.x += wgt[i] * x.x; o.y += wgt[i] * x.y;
                o.z += wgt[i] * x.z; o.w += wgt[i] * x.w;
            }
            dst[slot] = o;
        }
    }
    if (t == 0) {
        g_ml[(sp * BB + b) * 2]     = M;
        g_ml[(sp * BB + b) * 2 + 1] = L;
    }

    // ---- Fused combine: last split-CTA of this batch merges all 16 ----
    __threadfence();
    if (t == 0) isLast = (atomicAdd(&g_cnt_a[b], 1) == SPLIT - 1);
    __syncthreads();
    if (isLast) {
        __threadfence();   // acquire

        if (t < 32) {      // warp 0: lanes 0..15 own splits (16 <= 32)
            float mi = (t < SPLIT) ? g_ml[(t * BB + b) * 2]     : -1e30f;
            float li = (t < SPLIT) ? g_ml[(t * BB + b) * 2 + 1] : 0.f;
            float GM = mi;
            #pragma unroll
            for (int o = 16; o; o >>= 1)
                GM = fmaxf(GM, __shfl_xor_sync(0xffffffffu, GM, o));
            float gwi  = __expf(mi - GM);
            float term = li * gwi;
            #pragma unroll
            for (int o = 16; o; o >>= 1)
                term += __shfl_xor_sync(0xffffffffu, term, o);
            if (t < SPLIT) sgw[t] = gwi;
            if (t == 0) sInv = 1.f / term;
        }
        __syncthreads();

        const float inv = sInv;
        #pragma unroll
        for (int rep = 0; rep < 2; rep++) {
            int slot = t + rep * 128;
            if (slot < H4) {
                float4 o = make_float4(0.f, 0.f, 0.f, 0.f);
                #pragma unroll 4
                for (int i = 0; i < SPLIT; i++) {
                    float4 x = *((const float4*)(g_part + (size_t)(i * BB + b) * HH) + slot);
                    float gwi = sgw[i];
                    o.x += gwi * x.x; o.y += gwi * x.y;
                    o.z += gwi * x.z; o.w += gwi * x.w;
                }
                o.x *= inv; o.y *= inv; o.z *= inv; o.w *= inv;
                *((float4*)(out + (size_t)b * HH) + slot) = o;
            }
        }
        __syncthreads();
        if (t == 0) atomicExch(&g_cnt_a[b], 0);   // reset for graph replay
    }
}

// ---------------------------------------------------------------------------
extern "C" void kernel_launch(void* const* d_in, const int* in_sizes, int n_in,
                              void* d_out, int out_size)
{
    const float* h_tgt = (const float*)d_in[0];   // [64, 1, 1000]
    const float* h_src = (const float*)d_in[1];   // [64, 1024, 1000]
    const float* Wm    = (const float*)d_in[2];   // [1000, 1000]
    // d_in[3] = bias: cancels under softmax shift-invariance; unused.
    float* out = (float*)d_out;                   // [64, 1, 1000]

    v_kernel<<<dim3(16, VKS), 256>>>(h_tgt, Wm);
    attn_fused_kernel<<<dim3(SPLIT, BB), 128>>>(h_src, out);
}

// round 13
// speedup vs baseline: 1.2523x; 1.2523x over previous
#include <cuda_runtime.h>
#include <cstdint>

#define BB    64
#define SS    1024
#define HH    1000
#define SPLIT 16
#define CHUNK (SS / SPLIT)    /* 64 rows per CTA */
#define WPB   4               /* warps per block */
#define RPW   (CHUNK / WPB)   /* 16 rows per warp */
#define H4    250             /* float4 per row */

#define VKS   32              /* K-splits for v kernel (one CTA each) */
#define VGP   32              /* W rows per K-split (32*32=1024 >= 1000) */

// Scratch (static device arrays: allocation-free per harness rules)
__device__ __align__(16) float g_vp[VKS * BB * HH];     // 8 MB   v K-partials
__device__ __align__(16) float g_v[BB * HH];            // 256 KB v = h_tgt @ W
__device__ __align__(16) float g_part[SPLIT * BB * HH]; // 4 MB   acc per split
__device__ float g_ml[SPLIT * BB * 2];                  // (m, l) per split
__device__ int   g_cnt_v[16];                           // arrival ctr per h-chunk
__device__ int   g_cnt_a[BB];                           // arrival ctr per batch

// ---------------------------------------------------------------------------
// Kernel 1: v = h_tgt @ W. grid (16 h-chunks x 32 K-splits) = 512 CTAs.
// W read EXACTLY ONCE (4 MB) AND high parallelism: each thread does only
// ~32 independent LDG.128 iterations (R10's 125-serial-iter version was
// latency-bound at 128 CTAs). Last CTA per h-chunk reduces the 32 K-partials
// in fixed order (deterministic); partials are L2-resident (8 MB).
// ---------------------------------------------------------------------------
__global__ __launch_bounds__(256) void v_kernel(
    const float* __restrict__ h_tgt, const float* __restrict__ Wm)
{
    __shared__ float stg[64 * VGP];      // h_tgt slice [b][gi], 8 KB
    __shared__ int isLast;
    const int hb = blockIdx.x;           // 0..15
    const int ks = blockIdx.y;           // 0..31
    const int h0 = hb * 64, g0 = ks * VGP;
    const int gcnt = min(VGP, HH - g0);  // last split: 8
    const int t = threadIdx.x;

    for (int i = t; i < 64 * VGP; i += 256) {
        int b = i >> 5, gi = i & 31;
        int g = g0 + gi;
        stg[i] = (g < HH) ? h_tgt[b * HH + g] : 0.f;
    }
    __syncthreads();

    const int q = t & 15, bg = t >> 4;   // h-quad, batch-group(4)
    const int h = h0 + q * 4;
    const bool hok = (h + 3) < HH;

    if (hok) {
        float4 acc[4];
        #pragma unroll
        for (int i = 0; i < 4; i++) acc[i] = make_float4(0.f, 0.f, 0.f, 0.f);

        #pragma unroll 8
        for (int gi = 0; gi < gcnt; gi++) {
            float4 w4 = __ldg((const float4*)(Wm + (size_t)(g0 + gi) * HH + h));
            #pragma unroll
            for (int bb = 0; bb < 4; bb++) {
                float tb = stg[((bg << 2) + bb) * VGP + gi];
                acc[bb].x += tb * w4.x;
                acc[bb].y += tb * w4.y;
                acc[bb].z += tb * w4.z;
                acc[bb].w += tb * w4.w;
            }
        }
        #pragma unroll
        for (int bb = 0; bb < 4; bb++)
            *((float4*)(g_vp + ((size_t)ks * BB + (bg << 2) + bb) * HH + h)) = acc[bb];
    }

    __threadfence();
    if (t == 0) isLast = (atomicAdd(&g_cnt_v[hb], 1) == VKS - 1);
    __syncthreads();
    if (!isLast) return;
    __threadfence();   // acquire: see all K-partials

    // Reduce 32 partials for this h-chunk: 64 b x 16 h-quads = 1024 slots
    for (int slot = t; slot < 64 * 16; slot += 256) {
        int b = slot >> 4, qq = slot & 15;
        int h2 = h0 + qq * 4;
        if (h2 + 3 < HH) {
            float4 s = make_float4(0.f, 0.f, 0.f, 0.f);
            #pragma unroll
            for (int k = 0; k < VKS; k++) {
                float4 x = *((const float4*)(g_vp + ((size_t)k * BB + b) * HH + h2));
                s.x += x.x; s.y += x.y; s.z += x.z; s.w += x.w;
            }
            *((float4*)(g_v + (size_t)b * HH + h2)) = s;
        }
    }
    __syncthreads();
    if (t == 0) atomicExch(&g_cnt_v[hb], 0);   // reset for graph replay
}

// ---------------------------------------------------------------------------
// Kernel 2: warp-autonomous streaming attention + fused combine (unchanged
// from R10 attn: best measured at 60.7us / DRAM 55.8%).
// ---------------------------------------------------------------------------
__device__ __forceinline__ void load_row(float4 (&buf)[8],
                                         const float4* __restrict__ p, int lane)
{
    #pragma unroll
    for (int j = 0; j < 7; j++) buf[j] = __ldcg(p + lane + 32 * j);
    buf[7] = make_float4(0.f, 0.f, 0.f, 0.f);
    if (lane < 26) buf[7] = __ldcg(p + 224 + lane);
}

__global__ __launch_bounds__(128) void attn_fused_kernel(
    const float* __restrict__ h_src, float* __restrict__ out)
{
    __shared__ __align__(16) float sv[1024];   // 4 KB v
    __shared__ float4 sacc[WPB][256];          // 16 KB warp partials
    __shared__ float  sml[WPB][2];
    __shared__ float  sgw[SPLIT];
    __shared__ float  sInv;
    __shared__ int    isLast;

    const int sp = blockIdx.x, b = blockIdx.y;
    const int t = threadIdx.x, lane = t & 31, w = t >> 5;

    const float4* rp = (const float4*)(h_src +
        ((size_t)b * SS + (size_t)sp * CHUNK + (size_t)w * RPW) * HH);

    float4 A[8], B[8];
    load_row(A, rp, lane);               // pair 0 in flight before sv barrier
    load_row(B, rp + H4, lane);

    for (int i = t; i < HH; i += 128) sv[i] = g_v[b * HH + i];
    __syncthreads();
    const float4* v4 = (const float4*)sv;

    float m = -1e30f, l = 0.f;
    float4 acc[8];
    #pragma unroll
    for (int j = 0; j < 8; j++) acc[j] = make_float4(0.f, 0.f, 0.f, 0.f);

    #pragma unroll 1
    for (int i = 0; i < RPW; i += 2) {
        float sa0 = 0.f, sa1 = 0.f, sb0 = 0.f, sb1 = 0.f;
        #pragma unroll
        for (int j = 0; j < 7; j++) {
            float4 v = v4[lane + 32 * j];
            sa0 += A[j].x * v.x + A[j].z * v.z;
            sa1 += A[j].y * v.y + A[j].w * v.w;
            sb0 += B[j].x * v.x + B[j].z * v.z;
            sb1 += B[j].y * v.y + B[j].w * v.w;
        }
        if (lane < 26) {
            float4 v = v4[224 + lane];
            sa0 += A[7].x * v.x + A[7].z * v.z;
            sa1 += A[7].y * v.y + A[7].w * v.w;
            sb0 += B[7].x * v.x + B[7].z * v.z;
            sb1 += B[7].y * v.y + B[7].w * v.w;
        }
        float sA = sa0 + sa1, sB = sb0 + sb1;
        #pragma unroll
        for (int o = 16; o; o >>= 1) {
            sA += __shfl_xor_sync(0xffffffffu, sA, o);
            sB += __shfl_xor_sync(0xffffffffu, sB, o);
        }

        float nm   = fmaxf(m, fmaxf(sA, sB));
        float corr = __expf(m - nm);
        float pA   = __expf(sA - nm);
        float pB   = __expf(sB - nm);
        m = nm;
        l = l * corr + pA + pB;

        const bool more = (i + 2) < RPW;
        const float4* nA = more ? rp + 2 * H4 : rp;
        const float4* nB = more ? rp + 3 * H4 : rp;

        #pragma unroll
        for (int j = 0; j < 7; j++) {
            float4 a = A[j], bb = B[j];
            A[j] = __ldcg(nA + lane + 32 * j);
            B[j] = __ldcg(nB + lane + 32 * j);
            acc[j].x = acc[j].x * corr + pA * a.x + pB * bb.x;
            acc[j].y = acc[j].y * corr + pA * a.y + pB * bb.y;
            acc[j].z = acc[j].z * corr + pA * a.z + pB * bb.z;
            acc[j].w = acc[j].w * corr + pA * a.w + pB * bb.w;
        }
        {
            float4 a = A[7], bb = B[7];
            if (lane < 26) {
                A[7] = __ldcg(nA + 224 + lane);
                B[7] = __ldcg(nB + 224 + lane);
            }
            acc[7].x = acc[7].x * corr + pA * a.x + pB * bb.x;
            acc[7].y = acc[7].y * corr + pA * a.y + pB * bb.y;
            acc[7].z = acc[7].z * corr + pA * a.z + pB * bb.z;
            acc[7].w = acc[7].w * corr + pA * a.w + pB * bb.w;
        }
        rp += 2 * H4;
    }

    #pragma unroll
    for (int j = 0; j < 7; j++) sacc[w][lane + 32 * j] = acc[j];
    if (lane < 26) sacc[w][224 + lane] = acc[7];
    if (lane == 0) { sml[w][0] = m; sml[w][1] = l; }
    __syncthreads();

    float M = fmaxf(fmaxf(sml[0][0], sml[1][0]), fmaxf(sml[2][0], sml[3][0]));
    float L = 0.f;
    float wgt[WPB];
    #pragma unroll
    for (int i = 0; i < WPB; i++) {
        wgt[i] = __expf(sml[i][0] - M);
        L += sml[i][1] * wgt[i];
    }

    float4* dst = (float4*)(g_part + (size_t)(sp * BB + b) * HH);
    #pragma unroll
    for (int rep = 0; rep < 2; rep++) {
        int slot = t + rep * 128;
        if (slot < H4) {
            float4 o = make_float4(0.f, 0.f, 0.f, 0.f);
            #pragma unroll
            for (int i = 0; i < WPB; i++) {
                float4 x = sacc[i][slot];
                o.x += wgt[i] * x.x; o.y += wgt[i] * x.y;
                o.z += wgt[i] * x.z; o.w += wgt[i] * x.w;
            }
            dst[slot] = o;
        }
    }
    if (t == 0) {
        g_ml[(sp * BB + b) * 2]     = M;
        g_ml[(sp * BB + b) * 2 + 1] = L;
    }

    // ---- Fused combine: last split-CTA of this batch merges all 16 ----
    __threadfence();
    if (t == 0) isLast = (atomicAdd(&g_cnt_a[b], 1) == SPLIT - 1);
    __syncthreads();
    if (isLast) {
        __threadfence();   // acquire

        if (t < 32) {
            float mi = (t < SPLIT) ? g_ml[(t * BB + b) * 2]     : -1e30f;
            float li = (t < SPLIT) ? g_ml[(t * BB + b) * 2 + 1] : 0.f;
            float GM = mi;
            #pragma unroll
            for (int o = 16; o; o >>= 1)
                GM = fmaxf(GM, __shfl_xor_sync(0xffffffffu, GM, o));
            float gwi  = __expf(mi - GM);
            float term = li * gwi;
            #pragma unroll
            for (int o = 16; o; o >>= 1)
                term += __shfl_xor_sync(0xffffffffu, term, o);
            if (t < SPLIT) sgw[t] = gwi;
            if (t == 0) sInv = 1.f / term;
        }
        __syncthreads();

        const float inv = sInv;
        #pragma unroll
        for (int rep = 0; rep < 2; rep++) {
            int slot = t + rep * 128;
            if (slot < H4) {
                float4 o = make_float4(0.f, 0.f, 0.f, 0.f);
                #pragma unroll 4
                for (int i = 0; i < SPLIT; i++) {
                    float4 x = *((const float4*)(g_part + (size_t)(i * BB + b) * HH) + slot);
                    float gwi = sgw[i];
                    o.x += gwi * x.x; o.y += gwi * x.y;
                    o.z += gwi * x.z; o.w += gwi * x.w;
                }
                o.x *= inv; o.y *= inv; o.z *= inv; o.w *= inv;
                *((float4*)(out + (size_t)b * HH) + slot) = o;
            }
        }
        __syncthreads();
        if (t == 0) atomicExch(&g_cnt_a[b], 0);   // reset for graph replay
    }
}

// ---------------------------------------------------------------------------
extern "C" void kernel_launch(void* const* d_in, const int* in_sizes, int n_in,
                              void* d_out, int out_size)
{
    const float* h_tgt = (const float*)d_in[0];   // [64, 1, 1000]
    const float* h_src = (const float*)d_in[1];   // [64, 1024, 1000]
    const float* Wm    = (const float*)d_in[2];   // [1000, 1000]
    // d_in[3] = bias: cancels under softmax shift-invariance; unused.
    float* out = (float*)d_out;                   // [64, 1, 1000]

    v_kernel<<<dim3(16, VKS), 256>>>(h_tgt, Wm);
    attn_fused_kernel<<<dim3(SPLIT, BB), 128>>>(h_src, out);
}

// round 16
// speedup vs baseline: 1.7034x; 1.3603x over previous
#include <cuda_runtime.h>
#include <cstdint>

#define BB    64
#define SS    1024
#define HH    1000
#define SPLIT 16
#define CHUNK (SS / SPLIT)    /* 64 rows per CTA */
#define WPB   4               /* warps per block */
#define RPW   (CHUNK / WPB)   /* 16 rows per warp */
#define H4    250             /* float4 per row */

#define VKS   32              /* K-splits for v kernel (one CTA each) */
#define VGP   32              /* W rows per K-split (32*32=1024 >= 1000) */

// Scratch (static device arrays: allocation-free per harness rules)
__device__ __align__(16) float g_vp[VKS * BB * HH];     // 8 MB   v K-partials
__device__ __align__(16) float g_v[BB * HH];            // 256 KB v = h_tgt @ W
__device__ __align__(16) float g_part[SPLIT * BB * HH]; // 4 MB   acc per split
__device__ float g_ml[SPLIT * BB * 2];                  // (m, l) per split
__device__ int   g_cnt_a[BB];                           // arrival ctr per batch

// ---------------------------------------------------------------------------
// Kernel 1: v partials. grid (16 h-chunks x 32 K-splits) = 512 CTAs.
// W read EXACTLY ONCE (4 MB), ~32 unroll-8 LDG.128 iters/thread. PURE
// partial writes: no counter, no in-kernel reduce (R13 showed the last-CTA
// reduce ran on only 16 CTAs -> ~25us serialized tail).
// ---------------------------------------------------------------------------
__global__ __launch_bounds__(256) void v_partial_kernel(
    const float* __restrict__ h_tgt, const float* __restrict__ Wm)
{
    __shared__ float stg[64 * VGP];      // h_tgt slice [b][gi], 8 KB
    const int hb = blockIdx.x;           // 0..15
    const int ks = blockIdx.y;           // 0..31
    const int h0 = hb * 64, g0 = ks * VGP;
    const int gcnt = min(VGP, HH - g0);  // last split: 8
    const int t = threadIdx.x;

    for (int i = t; i < 64 * VGP; i += 256) {
        int b = i >> 5, gi = i & 31;
        int g = g0 + gi;
        stg[i] = (g < HH) ? h_tgt[b * HH + g] : 0.f;
    }
    __syncthreads();

    const int q = t & 15, bg = t >> 4;   // h-quad, batch-group(4)
    const int h = h0 + q * 4;
    if ((h + 3) >= HH) return;

    float4 acc[4];
    #pragma unroll
    for (int i = 0; i < 4; i++) acc[i] = make_float4(0.f, 0.f, 0.f, 0.f);

    #pragma unroll 8
    for (int gi = 0; gi < gcnt; gi++) {
        float4 w4 = __ldg((const float4*)(Wm + (size_t)(g0 + gi) * HH + h));
        #pragma unroll
        for (int bb = 0; bb < 4; bb++) {
            float tb = stg[((bg << 2) + bb) * VGP + gi];
            acc[bb].x += tb * w4.x;
            acc[bb].y += tb * w4.y;
            acc[bb].z += tb * w4.z;
            acc[bb].w += tb * w4.w;
        }
    }
    #pragma unroll
    for (int bb = 0; bb < 4; bb++)
        *((float4*)(g_vp + ((size_t)ks * BB + (bg << 2) + bb) * HH + h)) = acc[bb];
}

// ---------------------------------------------------------------------------
// Kernel 1b: WIDE reduce of the 32 K-partials. 250 CTAs x 256 threads,
// one float4 slot per thread (64*250 = 16000 slots). Fixed-order sum ->
// deterministic. 8 MB L2-resident read at chip bandwidth (~1-2 us).
// ---------------------------------------------------------------------------
__global__ __launch_bounds__(256) void v_reduce_kernel()
{
    int slot = blockIdx.x * 256 + threadIdx.x;   // 0 .. 16000-1
    if (slot >= BB * H4) return;
    int b = slot / H4, q = slot - b * H4;
    const float4* src = (const float4*)(g_vp + (size_t)b * HH) + q;
    float4 s = make_float4(0.f, 0.f, 0.f, 0.f);
    #pragma unroll 8
    for (int k = 0; k < VKS; k++) {
        float4 x = src[(size_t)k * (BB * HH) / 4];
        s.x += x.x; s.y += x.y; s.z += x.z; s.w += x.w;
    }
    *((float4*)(g_v + (size_t)b * HH) + q) = s;
}

// ---------------------------------------------------------------------------
// Kernel 2: warp-autonomous streaming attention + fused combine.
// BYTE-IDENTICAL to R10/R13 attn (best measured band 61-73us).
// ---------------------------------------------------------------------------
__device__ __forceinline__ void load_row(float4 (&buf)[8],
                                         const float4* __restrict__ p, int lane)
{
    #pragma unroll
    for (int j = 0; j < 7; j++) buf[j] = __ldcg(p + lane + 32 * j);
    buf[7] = make_float4(0.f, 0.f, 0.f, 0.f);
    if (lane < 26) buf[7] = __ldcg(p + 224 + lane);
}

__global__ __launch_bounds__(128) void attn_fused_kernel(
    const float* __restrict__ h_src, float* __restrict__ out)
{
    __shared__ __align__(16) float sv[1024];   // 4 KB v
    __shared__ float4 sacc[WPB][256];          // 16 KB warp partials
    __shared__ float  sml[WPB][2];
    __shared__ float  sgw[SPLIT];
    __shared__ float  sInv;
    __shared__ int    isLast;

    const int sp = blockIdx.x, b = blockIdx.y;
    const int t = threadIdx.x, lane = t & 31, w = t >> 5;

    const float4* rp = (const float4*)(h_src +
        ((size_t)b * SS + (size_t)sp * CHUNK + (size_t)w * RPW) * HH);

    float4 A[8], B[8];
    load_row(A, rp, lane);               // pair 0 in flight before sv barrier
    load_row(B, rp + H4, lane);

    for (int i = t; i < HH; i += 128) sv[i] = g_v[b * HH + i];
    __syncthreads();
    const float4* v4 = (const float4*)sv;

    float m = -1e30f, l = 0.f;
    float4 acc[8];
    #pragma unroll
    for (int j = 0; j < 8; j++) acc[j] = make_float4(0.f, 0.f, 0.f, 0.f);

    #pragma unroll 1
    for (int i = 0; i < RPW; i += 2) {
        float sa0 = 0.f, sa1 = 0.f, sb0 = 0.f, sb1 = 0.f;
        #pragma unroll
        for (int j = 0; j < 7; j++) {
            float4 v = v4[lane + 32 * j];
            sa0 += A[j].x * v.x + A[j].z * v.z;
            sa1 += A[j].y * v.y + A[j].w * v.w;
            sb0 += B[j].x * v.x + B[j].z * v.z;
            sb1 += B[j].y * v.y + B[j].w * v.w;
        }
        if (lane < 26) {
            float4 v = v4[224 + lane];
            sa0 += A[7].x * v.x + A[7].z * v.z;
            sa1 += A[7].y * v.y + A[7].w * v.w;
            sb0 += B[7].x * v.x + B[7].z * v.z;
            sb1 += B[7].y * v.y + B[7].w * v.w;
        }
        float sA = sa0 + sa1, sB = sb0 + sb1;
        #pragma unroll
        for (int o = 16; o; o >>= 1) {
            sA += __shfl_xor_sync(0xffffffffu, sA, o);
            sB += __shfl_xor_sync(0xffffffffu, sB, o);
        }

        float nm   = fmaxf(m, fmaxf(sA, sB));
        float corr = __expf(m - nm);
        float pA   = __expf(sA - nm);
        float pB   = __expf(sB - nm);
        m = nm;
        l = l * corr + pA + pB;

        const bool more = (i + 2) < RPW;
        const float4* nA = more ? rp + 2 * H4 : rp;
        const float4* nB = more ? rp + 3 * H4 : rp;

        #pragma unroll
        for (int j = 0; j < 7; j++) {
            float4 a = A[j], bb = B[j];
            A[j] = __ldcg(nA + lane + 32 * j);
            B[j] = __ldcg(nB + lane + 32 * j);
            acc[j].x = acc[j].x * corr + pA * a.x + pB * bb.x;
            acc[j].y = acc[j].y * corr + pA * a.y + pB * bb.y;
            acc[j].z = acc[j].z * corr + pA * a.z + pB * bb.z;
            acc[j].w = acc[j].w * corr + pA * a.w + pB * bb.w;
        }
        {
            float4 a = A[7], bb = B[7];
            if (lane < 26) {
                A[7] = __ldcg(nA + 224 + lane);
                B[7] = __ldcg(nB + 224 + lane);
            }
            acc[7].x = acc[7].x * corr + pA * a.x + pB * bb.x;
            acc[7].y = acc[7].y * corr + pA * a.y + pB * bb.y;
            acc[7].z = acc[7].z * corr + pA * a.z + pB * bb.z;
            acc[7].w = acc[7].w * corr + pA * a.w + pB * bb.w;
        }
        rp += 2 * H4;
    }

    #pragma unroll
    for (int j = 0; j < 7; j++) sacc[w][lane + 32 * j] = acc[j];
    if (lane < 26) sacc[w][224 + lane] = acc[7];
    if (lane == 0) { sml[w][0] = m; sml[w][1] = l; }
    __syncthreads();

    float M = fmaxf(fmaxf(sml[0][0], sml[1][0]), fmaxf(sml[2][0], sml[3][0]));
    float L = 0.f;
    float wgt[WPB];
    #pragma unroll
    for (int i = 0; i < WPB; i++) {
        wgt[i] = __expf(sml[i][0] - M);
        L += sml[i][1] * wgt[i];
    }

    float4* dst = (float4*)(g_part + (size_t)(sp * BB + b) * HH);
    #pragma unroll
    for (int rep = 0; rep < 2; rep++) {
        int slot = t + rep * 128;
        if (slot < H4) {
            float4 o = make_float4(0.f, 0.f, 0.f, 0.f);
            #pragma unroll
            for (int i = 0; i < WPB; i++) {
                float4 x = sacc[i][slot];
                o.x += wgt[i] * x.x; o.y += wgt[i] * x.y;
                o.z += wgt[i] * x.z; o.w += wgt[i] * x.w;
            }
            dst[slot] = o;
        }
    }
    if (t == 0) {
        g_ml[(sp * BB + b) * 2]     = M;
        g_ml[(sp * BB + b) * 2 + 1] = L;
    }

    // ---- Fused combine: last split-CTA of this batch merges all 16 ----
    __threadfence();
    if (t == 0) isLast = (atomicAdd(&g_cnt_a[b], 1) == SPLIT - 1);
    __syncthreads();
    if (isLast) {
        __threadfence();   // acquire

        if (t < 32) {
            float mi = (t < SPLIT) ? g_ml[(t * BB + b) * 2]     : -1e30f;
            float li = (t < SPLIT) ? g_ml[(t * BB + b) * 2 + 1] : 0.f;
            float GM = mi;
            #pragma unroll
            for (int o = 16; o; o >>= 1)
                GM = fmaxf(GM, __shfl_xor_sync(0xffffffffu, GM, o));
            float gwi  = __expf(mi - GM);
            float term = li * gwi;
            #pragma unroll
            for (int o = 16; o; o >>= 1)
                term += __shfl_xor_sync(0xffffffffu, term, o);
            if (t < SPLIT) sgw[t] = gwi;
            if (t == 0) sInv = 1.f / term;
        }
        __syncthreads();

        const float inv = sInv;
        #pragma unroll
        for (int rep = 0; rep < 2; rep++) {
            int slot = t + rep * 128;
            if (slot < H4) {
                float4 o = make_float4(0.f, 0.f, 0.f, 0.f);
                #pragma unroll 4
                for (int i = 0; i < SPLIT; i++) {
                    float4 x = *((const float4*)(g_part + (size_t)(i * BB + b) * HH) + slot);
                    float gwi = sgw[i];
                    o.x += gwi * x.x; o.y += gwi * x.y;
                    o.z += gwi * x.z; o.w += gwi * x.w;
                }
                o.x *= inv; o.y *= inv; o.z *= inv; o.w *= inv;
                *((float4*)(out + (size_t)b * HH) + slot) = o;
            }
        }
        __syncthreads();
        if (t == 0) atomicExch(&g_cnt_a[b], 0);   // reset for graph replay
    }
}

// ---------------------------------------------------------------------------
extern "C" void kernel_launch(void* const* d_in, const int* in_sizes, int n_in,
                              void* d_out, int out_size)
{
    const float* h_tgt = (const float*)d_in[0];   // [64, 1, 1000]
    const float* h_src = (const float*)d_in[1];   // [64, 1024, 1000]
    const float* Wm    = (const float*)d_in[2];   // [1000, 1000]
    // d_in[3] = bias: cancels under softmax shift-invariance; unused.
    float* out = (float*)d_out;                   // [64, 1, 1000]

    v_partial_kernel<<<dim3(16, VKS), 256>>>(h_tgt, Wm);
    v_reduce_kernel<<<(BB * H4 + 255) / 256, 256>>>();
    attn_fused_kernel<<<dim3(SPLIT, BB), 128>>>(h_src, out);
}